// round 2
// baseline (speedup 1.0000x reference)
#include <cuda_runtime.h>
#include <cuda_bf16.h>
#include <math_constants.h>
#include <cfloat>

// Problem constants (fixed by the dataset)
#define NN 50000
#define EE 800000
#define ET (EE + NN)        // edges + self-loops
#define IND 64              // input dim (both layers: 64)
#define HXC 128             // H*C = 2*64
#define HIDD 64
#define OUTD 32

// -------- scratch (device globals; no allocation allowed) --------
__device__ float g_xl[NN * HXC];     // transformed features [N,128]
__device__ float g_asrc[NN * 2];     // per-node per-head src attention
__device__ float g_adst[NN * 2];
__device__ int   g_amax[NN * 2];     // ordered-int encoded segment max
__device__ float g_denom[NN * 2];
__device__ float g_w[ET * 2];        // exp(alpha - amax[dst]) per edge/head
__device__ float g_agg[NN * HXC];    // aggregation accumulator
__device__ float g_h[NN * HIDD];     // post-FC hidden

// -------- helpers --------
__device__ __forceinline__ int f2o(float f) {
    int i = __float_as_int(f);
    return (i >= 0) ? i : (i ^ 0x7fffffff);
}
__device__ __forceinline__ float o2f(int i) {
    return __int_as_float((i >= 0) ? i : (i ^ 0x7fffffff));
}
__device__ __forceinline__ float lrelu(float x) {
    return (x >= 0.f) ? x : 0.2f * x;
}
__device__ __forceinline__ void red_add_v4(float* addr, float4 v) {
    asm volatile("red.global.add.v4.f32 [%0], {%1,%2,%3,%4};"
                 :: "l"(addr), "f"(v.x), "f"(v.y), "f"(v.z), "f"(v.w)
                 : "memory");
}

// -------- K1: xl = x @ W  (x: [N,64], W: [64,128]) --------
// 64 nodes per block, 128 threads (one per output col)
__global__ void feat_kernel(const float* __restrict__ x, const float* __restrict__ W) {
    __shared__ float xs[64][64];      // 16 KB
    __shared__ float ws[64][128];     // 32 KB
    int n0 = blockIdx.x * 64;
    int tid = threadIdx.x;
    for (int i = tid; i < 64 * 128; i += 128) ws[i >> 7][i & 127] = W[i];
    for (int i = tid; i < 64 * 64; i += 128) {
        int r = i >> 6, c = i & 63;
        xs[r][c] = (n0 + r < NN) ? x[(n0 + r) * IND + c] : 0.f;
    }
    __syncthreads();
    int col = tid;
    int nmax = min(64, NN - n0);
    for (int i = 0; i < nmax; i++) {
        float acc = 0.f;
#pragma unroll
        for (int k = 0; k < 64; k++) acc += xs[i][k] * ws[k][col];
        g_xl[(n0 + i) * HXC + col] = acc;
    }
}

// -------- K2: per-node attention dots a_src/a_dst --------
// warp per node; lane holds 4 cols of xl row
__global__ void att_kernel(const float* __restrict__ att_src, const float* __restrict__ att_dst) {
    int lane = threadIdx.x & 31;
    int n = blockIdx.x * 8 + (threadIdx.x >> 5);
    if (n >= NN) return;
    const float* row = &g_xl[n * HXC];
    float v0 = row[lane], v1 = row[lane + 32], v2 = row[lane + 64], v3 = row[lane + 96];
    float s0 = v0 * att_src[lane] + v1 * att_src[lane + 32];
    float s1 = v2 * att_src[lane + 64] + v3 * att_src[lane + 96];
    float d0 = v0 * att_dst[lane] + v1 * att_dst[lane + 32];
    float d1 = v2 * att_dst[lane + 64] + v3 * att_dst[lane + 96];
#pragma unroll
    for (int o = 16; o > 0; o >>= 1) {
        s0 += __shfl_xor_sync(0xffffffffu, s0, o);
        s1 += __shfl_xor_sync(0xffffffffu, s1, o);
        d0 += __shfl_xor_sync(0xffffffffu, d0, o);
        d1 += __shfl_xor_sync(0xffffffffu, d1, o);
    }
    if (lane == 0) {
        g_asrc[n * 2 + 0] = s0; g_asrc[n * 2 + 1] = s1;
        g_adst[n * 2 + 0] = d0; g_adst[n * 2 + 1] = d1;
    }
}

// -------- K3: init accumulators --------
__global__ void init_kernel() {
    int i = blockIdx.x * blockDim.x + threadIdx.x;
    if (i < NN * HXC) g_agg[i] = 0.f;
    if (i < NN * 2) { g_amax[i] = f2o(-FLT_MAX); g_denom[i] = 0.f; }
}

// -------- K4: segment max over edges (incl self-loops) --------
__global__ void edge_max_kernel(const int* __restrict__ ei) {
    int e = blockIdx.x * blockDim.x + threadIdx.x;
    if (e >= ET) return;
    int s, d;
    if (e < EE) { s = ei[e]; d = ei[EE + e]; } else { s = d = e - EE; }
#pragma unroll
    for (int h = 0; h < 2; h++) {
        float a = lrelu(g_asrc[s * 2 + h] + g_adst[d * 2 + h]);
        atomicMax(&g_amax[d * 2 + h], f2o(a));
    }
}

// -------- K5: exp + denom --------
__global__ void edge_exp_kernel(const int* __restrict__ ei) {
    int e = blockIdx.x * blockDim.x + threadIdx.x;
    if (e >= ET) return;
    int s, d;
    if (e < EE) { s = ei[e]; d = ei[EE + e]; } else { s = d = e - EE; }
#pragma unroll
    for (int h = 0; h < 2; h++) {
        float a = lrelu(g_asrc[s * 2 + h] + g_adst[d * 2 + h]);
        float w = expf(a - o2f(g_amax[d * 2 + h]));
        g_w[e * 2 + h] = w;
        atomicAdd(&g_denom[d * 2 + h], w);
    }
}

// -------- K6: message pass. warp per edge; lane handles one float4 chunk --------
__global__ void msg_kernel(const int* __restrict__ ei) {
    int tid = blockIdx.x * blockDim.x + threadIdx.x;
    int e = tid >> 5;
    if (e >= ET) return;
    int j = tid & 31;          // 0..31 -> 4 floats each
    int h = j >> 4;            // head
    int s, d;
    if (e < EE) { s = ei[e]; d = ei[EE + e]; } else { s = d = e - EE; }
    float w = g_w[e * 2 + h] / (g_denom[d * 2 + h] + 1e-16f);
    const float4* xl4 = (const float4*)g_xl;
    float4 v = xl4[s * 32 + j];
    v.x *= w; v.y *= w; v.z *= w; v.w *= w;
    red_add_v4(&g_agg[d * HXC + j * 4], v);
}

// -------- K7: out = elu(agg + bias) @ fcw + fcb  ([N,128] -> [N,64]) --------
// 32 nodes per block, 64 threads (one per output col)
__global__ void post_kernel(const float* __restrict__ bias,
                            const float* __restrict__ fcw,
                            const float* __restrict__ fcb) {
    __shared__ float fws[128][64];    // 32 KB
    __shared__ float tile[32][128];   // 16 KB
    int n0 = blockIdx.x * 32;
    int tid = threadIdx.x;  // 64
    for (int i = tid; i < 128 * 64; i += 64) fws[i >> 6][i & 63] = fcw[i];
    for (int i = tid; i < 32 * 128; i += 64) {
        int r = i >> 7, c = i & 127;
        float v = 0.f;
        if (n0 + r < NN) {
            v = g_agg[(n0 + r) * HXC + c] + bias[c];
            v = (v > 0.f) ? v : expm1f(v);   // ELU
        }
        tile[r][c] = v;
    }
    __syncthreads();
    int col = tid;
    int nmax = min(32, NN - n0);
    for (int i = 0; i < nmax; i++) {
        float acc = fcb[col];
#pragma unroll
        for (int k = 0; k < 128; k++) acc += tile[i][k] * fws[k][col];
        g_h[(n0 + i) * HIDD + col] = acc;
    }
}

// -------- K8: logits -> gumbel -> softmax. warp per node, lane = out col --------
__global__ void final_kernel(const float* __restrict__ ow,
                             const float* __restrict__ ob,
                             const float* __restrict__ gu,
                             float* __restrict__ out) {
    __shared__ float ows[64 * 32];
    int tid = threadIdx.x;
    for (int i = tid; i < 64 * 32; i += 256) ows[i] = ow[i];
    __syncthreads();
    int lane = tid & 31;
    int n = blockIdx.x * 8 + (tid >> 5);
    if (n >= NN) return;
    float hlo = g_h[n * HIDD + lane];
    float hhi = g_h[n * HIDD + 32 + lane];
    float acc = ob[lane];
#pragma unroll
    for (int k = 0; k < 32; k++)
        acc += __shfl_sync(0xffffffffu, hlo, k) * ows[k * 32 + lane];
#pragma unroll
    for (int k = 0; k < 32; k++)
        acc += __shfl_sync(0xffffffffu, hhi, k) * ows[(32 + k) * 32 + lane];
    float u = gu[n * OUTD + lane];
    float g = -logf(-logf(u + 1e-20f) + 1e-20f);
    float z = acc + g;   // TEMP = 1
    float m = z;
#pragma unroll
    for (int o = 16; o > 0; o >>= 1) m = fmaxf(m, __shfl_xor_sync(0xffffffffu, m, o));
    float e = expf(z - m);
    float ssum = e;
#pragma unroll
    for (int o = 16; o > 0; o >>= 1) ssum += __shfl_xor_sync(0xffffffffu, ssum, o);
    out[n * OUTD + lane] = e / ssum;
}

// -------- orchestration --------
static void run_gat_layer(const float* x, const int* ei,
                          const float* W, const float* asrc, const float* adst,
                          const float* bias, const float* fcw, const float* fcb) {
    feat_kernel<<<(NN + 63) / 64, 128>>>(x, W);
    att_kernel<<<(NN + 7) / 8, 256>>>(asrc, adst);
    init_kernel<<<(NN * HXC + 255) / 256, 256>>>();
    edge_max_kernel<<<(ET + 255) / 256, 256>>>(ei);
    edge_exp_kernel<<<(ET + 255) / 256, 256>>>(ei);
    {
        long long t = (long long)ET * 32;
        msg_kernel<<<(int)((t + 255) / 256), 256>>>(ei);
    }
    post_kernel<<<(NN + 31) / 32, 64>>>(bias, fcw, fcb);
}

extern "C" void kernel_launch(void* const* d_in, const int* in_sizes, int n_in,
                              void* d_out, int out_size) {
    const float* x      = (const float*)d_in[0];
    const int*   ei     = (const int*)d_in[1];
    const float* W0     = (const float*)d_in[2];
    const float* asrc0  = (const float*)d_in[3];
    const float* adst0  = (const float*)d_in[4];
    const float* bias0  = (const float*)d_in[5];
    const float* fcw0   = (const float*)d_in[6];
    const float* fcb0   = (const float*)d_in[7];
    const float* W1     = (const float*)d_in[8];
    const float* asrc1  = (const float*)d_in[9];
    const float* adst1  = (const float*)d_in[10];
    const float* bias1  = (const float*)d_in[11];
    const float* fcw1   = (const float*)d_in[12];
    const float* fcb1   = (const float*)d_in[13];
    const float* out_w  = (const float*)d_in[14];
    const float* out_b  = (const float*)d_in[15];
    const float* gu     = (const float*)d_in[16];
    float* out = (float*)d_out;

    // Layer 1: input x [N,64]
    run_gat_layer(x, ei, W0, asrc0, adst0, bias0, fcw0, fcb0);
    // Layer 2: input g_h [N,64]
    {
        // g_h is read by feat_kernel before post_kernel of layer 2 rewrites it
        float* hin;
        cudaGetSymbolAddress((void**)&hin, g_h);
        run_gat_layer(hin, ei, W1, asrc1, adst1, bias1, fcw1, fcb1);
    }
    // Final head
    final_kernel<<<(NN + 7) / 8, 256>>>(out_w, out_b, gu, out);
}

// round 3
// speedup vs baseline: 1.4866x; 1.4866x over previous
#include <cuda_runtime.h>
#include <cuda_bf16.h>
#include <cfloat>

// Problem constants (fixed by the dataset)
#define NN 50000
#define EE 800000
#define ET (EE + NN)        // edges + self-loops
#define HXC 128             // H*C = 2*64
#define HIDD 64
#define OUTD 32

// -------- scratch (device globals; no allocation allowed) --------
__device__ float g_xl[NN * HXC];     // transformed features [N,128]
__device__ float g_asrc[NN * 2];     // per-node per-head attention dots
__device__ float g_adst[NN * 2];
__device__ float g_agg[NN * HXC];    // normalized aggregation output
__device__ float g_h[NN * HIDD];     // post-FC hidden
__device__ int   g_deg[NN];          // CSR build
__device__ int   g_off[NN + 1];
__device__ int   g_cur[NN];
__device__ int   g_csr[ET];          // src index per (dst-sorted) edge

__device__ __forceinline__ float lrelu(float x) {
    return (x >= 0.f) ? x : 0.2f * x;
}

// ================= CSR build (once per launch; edge_index shared by layers) =================
__global__ void zero_deg_kernel() {
    int i = blockIdx.x * blockDim.x + threadIdx.x;
    if (i < NN) g_deg[i] = 1;   // self-loop
}
__global__ void hist_kernel(const int* __restrict__ ei) {
    int e = blockIdx.x * blockDim.x + threadIdx.x;
    if (e < EE) atomicAdd(&g_deg[ei[EE + e]], 1);
}
__global__ void scan_kernel() {     // single block, 1024 threads
    __shared__ int part[1024];
    const int CH = (NN + 1023) / 1024;      // 49
    int t = threadIdx.x;
    int b = t * CH;
    int e = min(b + CH, NN);
    int sum = 0;
    for (int i = b; i < e; i++) sum += g_deg[i];
    part[t] = sum;
    __syncthreads();
    for (int o = 1; o < 1024; o <<= 1) {
        int v = (t >= o) ? part[t - o] : 0;
        __syncthreads();
        part[t] += v;
        __syncthreads();
    }
    int run = (t == 0) ? 0 : part[t - 1];
    for (int i = b; i < e; i++) {
        g_off[i] = run;
        g_cur[i] = run;
        run += g_deg[i];
    }
    if (t == 1023) g_off[NN] = run;
}
__global__ void scatter_kernel(const int* __restrict__ ei) {
    int e = blockIdx.x * blockDim.x + threadIdx.x;
    if (e >= ET) return;
    int s, d;
    if (e < EE) { s = ei[e]; d = ei[EE + e]; } else { s = d = e - EE; }
    int pos = atomicAdd(&g_cur[d], 1);
    g_csr[pos] = s;
}

// ================= K1: xl = x @ W  (x:[N,64], W:[64,128]) =================
// 64 nodes/block, 128 threads; W column held in registers; FFMA-floor bound.
__global__ void feat_kernel(const float* __restrict__ x, const float* __restrict__ W) {
    __shared__ float ws[64 * 128];    // 32 KB
    __shared__ float xs[64][64];      // 16 KB
    int tid = threadIdx.x;
    int n0 = blockIdx.x * 64;
    for (int i = tid; i < 64 * 128; i += 128) ws[i] = W[i];
    for (int i = tid; i < 64 * 64; i += 128) {
        int r = i >> 6, c = i & 63;
        xs[r][c] = (n0 + r < NN) ? x[(n0 + r) * 64 + c] : 0.f;
    }
    __syncthreads();
    int col = tid;
    float wreg[64];
#pragma unroll
    for (int k = 0; k < 64; k++) wreg[k] = ws[k * 128 + col];
    for (int t = 0; t < 4; t++) {
        float acc[16];
#pragma unroll
        for (int i = 0; i < 16; i++) acc[i] = 0.f;
#pragma unroll
        for (int i = 0; i < 16; i++) {
            const float4* xr = (const float4*)xs[t * 16 + i];
#pragma unroll
            for (int k4 = 0; k4 < 16; k4++) {
                float4 v = xr[k4];
                acc[i] += v.x * wreg[k4 * 4] + v.y * wreg[k4 * 4 + 1]
                        + v.z * wreg[k4 * 4 + 2] + v.w * wreg[k4 * 4 + 3];
            }
        }
        int base = n0 + t * 16;
        int nmax = min(16, NN - base);
        for (int i = 0; i < nmax; i++) g_xl[(base + i) * HXC + col] = acc[i];
    }
}

// ================= K2: per-node attention dots =================
__global__ void att_kernel(const float* __restrict__ att_src, const float* __restrict__ att_dst) {
    int lane = threadIdx.x & 31;
    int n = blockIdx.x * 8 + (threadIdx.x >> 5);
    if (n >= NN) return;
    const float* row = &g_xl[n * HXC];
    float v0 = row[lane], v1 = row[lane + 32], v2 = row[lane + 64], v3 = row[lane + 96];
    float s0 = v0 * att_src[lane] + v1 * att_src[lane + 32];
    float s1 = v2 * att_src[lane + 64] + v3 * att_src[lane + 96];
    float d0 = v0 * att_dst[lane] + v1 * att_dst[lane + 32];
    float d1 = v2 * att_dst[lane + 64] + v3 * att_dst[lane + 96];
#pragma unroll
    for (int o = 16; o > 0; o >>= 1) {
        s0 += __shfl_xor_sync(0xffffffffu, s0, o);
        s1 += __shfl_xor_sync(0xffffffffu, s1, o);
        d0 += __shfl_xor_sync(0xffffffffu, d0, o);
        d1 += __shfl_xor_sync(0xffffffffu, d1, o);
    }
    if (lane == 0) {
        g_asrc[n * 2 + 0] = s0; g_asrc[n * 2 + 1] = s1;
        g_adst[n * 2 + 0] = d0; g_adst[n * 2 + 1] = d1;
    }
}

// ================= K3: fused softmax + gather aggregation (warp per dst) =================
__global__ void agg_kernel() {
    int warp = (blockIdx.x * blockDim.x + threadIdx.x) >> 5;
    int lane = threadIdx.x & 31;
    if (warp >= NN) return;
    int n = warp;
    int o0 = g_off[n], o1 = g_off[n + 1];
    int cnt = o1 - o0;
    float2 ad = ((const float2*)g_adst)[n];
    int h = lane >> 4;                   // head for this lane's 4 columns
    float4 acc = make_float4(0.f, 0.f, 0.f, 0.f);
    float dw0 = 0.f, dw1 = 0.f;
    const float4* xl4 = (const float4*)g_xl;

    if (cnt <= 32) {
        // fast path: whole edge list fits in one warp chunk; single gather of asrc
        int s_l = 0;
        float a0 = -FLT_MAX, a1 = -FLT_MAX;
        if (lane < cnt) {
            s_l = g_csr[o0 + lane];
            float2 as = ((const float2*)g_asrc)[s_l];
            a0 = lrelu(as.x + ad.x);
            a1 = lrelu(as.y + ad.y);
        }
        float m0 = a0, m1 = a1;
#pragma unroll
        for (int o = 16; o > 0; o >>= 1) {
            m0 = fmaxf(m0, __shfl_xor_sync(0xffffffffu, m0, o));
            m1 = fmaxf(m1, __shfl_xor_sync(0xffffffffu, m1, o));
        }
        float w0_l = 0.f, w1_l = 0.f;
        if (lane < cnt) {
            w0_l = expf(a0 - m0);
            w1_l = expf(a1 - m1);
            dw0 = w0_l; dw1 = w1_l;
        }
        for (int j = 0; j < cnt; j++) {
            int s = __shfl_sync(0xffffffffu, s_l, j);
            float w0 = __shfl_sync(0xffffffffu, w0_l, j);
            float w1 = __shfl_sync(0xffffffffu, w1_l, j);
            float4 v = xl4[s * 32 + lane];
            float w = h ? w1 : w0;
            acc.x += w * v.x; acc.y += w * v.y; acc.z += w * v.z; acc.w += w * v.w;
        }
    } else {
        // generic path: two passes over the edge list
        float m0 = -FLT_MAX, m1 = -FLT_MAX;
        for (int i = o0 + lane; i < o1; i += 32) {
            int s = g_csr[i];
            float2 as = ((const float2*)g_asrc)[s];
            m0 = fmaxf(m0, lrelu(as.x + ad.x));
            m1 = fmaxf(m1, lrelu(as.y + ad.y));
        }
#pragma unroll
        for (int o = 16; o > 0; o >>= 1) {
            m0 = fmaxf(m0, __shfl_xor_sync(0xffffffffu, m0, o));
            m1 = fmaxf(m1, __shfl_xor_sync(0xffffffffu, m1, o));
        }
        for (int base = o0; base < o1; base += 32) {
            int c = min(32, o1 - base);
            int s_l = 0;
            float w0_l = 0.f, w1_l = 0.f;
            if (lane < c) {
                s_l = g_csr[base + lane];
                float2 as = ((const float2*)g_asrc)[s_l];
                w0_l = expf(lrelu(as.x + ad.x) - m0);
                w1_l = expf(lrelu(as.y + ad.y) - m1);
                dw0 += w0_l; dw1 += w1_l;
            }
            for (int j = 0; j < c; j++) {
                int s = __shfl_sync(0xffffffffu, s_l, j);
                float w0 = __shfl_sync(0xffffffffu, w0_l, j);
                float w1 = __shfl_sync(0xffffffffu, w1_l, j);
                float4 v = xl4[s * 32 + lane];
                float w = h ? w1 : w0;
                acc.x += w * v.x; acc.y += w * v.y; acc.z += w * v.z; acc.w += w * v.w;
            }
        }
    }
#pragma unroll
    for (int o = 16; o > 0; o >>= 1) {
        dw0 += __shfl_xor_sync(0xffffffffu, dw0, o);
        dw1 += __shfl_xor_sync(0xffffffffu, dw1, o);
    }
    float denom = (h ? dw1 : dw0) + 1e-16f;
    float inv = 1.f / denom;
    ((float4*)g_agg)[n * 32 + lane] =
        make_float4(acc.x * inv, acc.y * inv, acc.z * inv, acc.w * inv);
}

// ================= K4: h = elu(agg + bias) @ fcw + fcb  ([N,128] -> [N,64]) =================
// 32 nodes/block, 128 threads; k split across 2 halves, fcw in registers.
__global__ void post_kernel(const float* __restrict__ bias,
                            const float* __restrict__ fcw,
                            const float* __restrict__ fcb) {
    __shared__ float tile[32][128];   // 16 KB
    __shared__ float part[32][64];    // 8 KB
    int tid = threadIdx.x;            // 128
    int n0 = blockIdx.x * 32;
    int col = tid & 63, kh = tid >> 6;
    float fwreg[64];
#pragma unroll
    for (int k = 0; k < 64; k++) fwreg[k] = fcw[(kh * 64 + k) * 64 + col];
    for (int i = tid; i < 32 * 128; i += 128) {
        int r = i >> 7, c = i & 127;
        float v = 0.f;
        if (n0 + r < NN) {
            v = g_agg[(n0 + r) * HXC + c] + bias[c];
            v = (v > 0.f) ? v : expm1f(v);   // ELU
        }
        tile[r][c] = v;
    }
    __syncthreads();
    float acc[32];
#pragma unroll
    for (int i = 0; i < 32; i++) acc[i] = 0.f;
#pragma unroll 4
    for (int i = 0; i < 32; i++) {
        const float4* tr = (const float4*)&tile[i][kh * 64];
#pragma unroll
        for (int k4 = 0; k4 < 16; k4++) {
            float4 v = tr[k4];
            acc[i] += v.x * fwreg[k4 * 4] + v.y * fwreg[k4 * 4 + 1]
                    + v.z * fwreg[k4 * 4 + 2] + v.w * fwreg[k4 * 4 + 3];
        }
    }
    if (kh == 1) {
#pragma unroll 4
        for (int i = 0; i < 32; i++) part[i][col] = acc[i];
    }
    __syncthreads();
    if (kh == 0) {
        int nmax = min(32, NN - n0);
        float b = fcb[col];
        for (int i = 0; i < nmax; i++)
            g_h[(n0 + i) * HIDD + col] = acc[i] + part[i][col] + b;
    }
}

// ================= K5: logits -> gumbel -> softmax (warp per node) =================
__global__ void final_kernel(const float* __restrict__ ow,
                             const float* __restrict__ ob,
                             const float* __restrict__ gu,
                             float* __restrict__ out) {
    __shared__ float ows[64 * 32];
    int tid = threadIdx.x;
    for (int i = tid; i < 64 * 32; i += 256) ows[i] = ow[i];
    __syncthreads();
    int lane = tid & 31;
    int n = blockIdx.x * 8 + (tid >> 5);
    if (n >= NN) return;
    float hlo = g_h[n * HIDD + lane];
    float hhi = g_h[n * HIDD + 32 + lane];
    float acc = ob[lane];
#pragma unroll
    for (int k = 0; k < 32; k++)
        acc += __shfl_sync(0xffffffffu, hlo, k) * ows[k * 32 + lane];
#pragma unroll
    for (int k = 0; k < 32; k++)
        acc += __shfl_sync(0xffffffffu, hhi, k) * ows[(32 + k) * 32 + lane];
    float u = gu[n * OUTD + lane];
    float g = -logf(-logf(u + 1e-20f) + 1e-20f);
    float z = acc + g;   // TEMP = 1
    float m = z;
#pragma unroll
    for (int o = 16; o > 0; o >>= 1) m = fmaxf(m, __shfl_xor_sync(0xffffffffu, m, o));
    float e = expf(z - m);
    float ssum = e;
#pragma unroll
    for (int o = 16; o > 0; o >>= 1) ssum += __shfl_xor_sync(0xffffffffu, ssum, o);
    out[n * OUTD + lane] = e / ssum;
}

// ================= orchestration =================
static void run_gat_layer(const float* x,
                          const float* W, const float* asrc, const float* adst,
                          const float* bias, const float* fcw, const float* fcb) {
    feat_kernel<<<(NN + 63) / 64, 128>>>(x, W);
    att_kernel<<<(NN + 7) / 8, 256>>>(asrc, adst);
    agg_kernel<<<(NN + 7) / 8, 256>>>();
    post_kernel<<<(NN + 31) / 32, 128>>>(bias, fcw, fcb);
}

extern "C" void kernel_launch(void* const* d_in, const int* in_sizes, int n_in,
                              void* d_out, int out_size) {
    const float* x      = (const float*)d_in[0];
    const int*   ei     = (const int*)d_in[1];
    const float* W0     = (const float*)d_in[2];
    const float* asrc0  = (const float*)d_in[3];
    const float* adst0  = (const float*)d_in[4];
    const float* bias0  = (const float*)d_in[5];
    const float* fcw0   = (const float*)d_in[6];
    const float* fcb0   = (const float*)d_in[7];
    const float* W1     = (const float*)d_in[8];
    const float* asrc1  = (const float*)d_in[9];
    const float* adst1  = (const float*)d_in[10];
    const float* bias1  = (const float*)d_in[11];
    const float* fcw1   = (const float*)d_in[12];
    const float* fcb1   = (const float*)d_in[13];
    const float* out_w  = (const float*)d_in[14];
    const float* out_b  = (const float*)d_in[15];
    const float* gu     = (const float*)d_in[16];
    float* out = (float*)d_out;

    // CSR build (edge_index identical for both layers)
    zero_deg_kernel<<<(NN + 255) / 256, 256>>>();
    hist_kernel<<<(EE + 255) / 256, 256>>>(ei);
    scan_kernel<<<1, 1024>>>();
    scatter_kernel<<<(ET + 255) / 256, 256>>>(ei);

    // Layer 1
    run_gat_layer(x, W0, asrc0, adst0, bias0, fcw0, fcb0);
    // Layer 2 (input = g_h)
    {
        float* hin;
        cudaGetSymbolAddress((void**)&hin, g_h);
        run_gat_layer(hin, W1, asrc1, adst1, bias1, fcw1, fcb1);
    }
    // Final head
    final_kernel<<<(NN + 7) / 8, 256>>>(out_w, out_b, gu, out);
}

// round 4
// speedup vs baseline: 1.7679x; 1.1892x over previous
#include <cuda_runtime.h>
#include <cuda_bf16.h>
#include <cfloat>

// Problem constants (fixed by the dataset)
#define NN 50000
#define EE 800000
#define ET (EE + NN)        // edges + self-loops
#define HXC 128             // H*C = 2*64
#define HIDD 64
#define OUTD 32

#define SCAN_BLK 256
#define NBLK ((NN + SCAN_BLK - 1) / SCAN_BLK)   // 196

// -------- scratch (device globals; no allocation allowed) --------
__device__ float g_xl[NN * HXC];     // transformed features [N,128]
__device__ float g_asrc[NN * 2];     // per-node per-head attention dots
__device__ float g_adst[NN * 2];
__device__ float g_agg[NN * HXC];    // normalized aggregation output
__device__ float g_h[NN * HIDD];     // post-FC hidden
__device__ int   g_deg[NN];          // CSR build
__device__ int   g_off[NN + 1];
__device__ int   g_cur[NN];
__device__ int   g_csr[ET];          // src index per (dst-sorted) edge
__device__ int   g_bsum[NBLK];
__device__ int   g_boff[NBLK];

__device__ __forceinline__ float lrelu(float x) {
    return (x >= 0.f) ? x : 0.2f * x;
}

// ================= CSR build =================
__global__ void zero_deg_kernel() {
    int i = blockIdx.x * blockDim.x + threadIdx.x;
    if (i < NN) g_deg[i] = 1;   // self-loop
}
__global__ void hist_kernel(const int* __restrict__ ei) {
    int e = blockIdx.x * blockDim.x + threadIdx.x;
    if (e < EE) atomicAdd(&g_deg[ei[EE + e]], 1);
}
// block sums
__global__ void scan1_kernel() {
    __shared__ int sh[SCAN_BLK];
    int i = blockIdx.x * SCAN_BLK + threadIdx.x;
    int v = (i < NN) ? g_deg[i] : 0;
    sh[threadIdx.x] = v;
    __syncthreads();
    for (int o = SCAN_BLK / 2; o > 0; o >>= 1) {
        if (threadIdx.x < o) sh[threadIdx.x] += sh[threadIdx.x + o];
        __syncthreads();
    }
    if (threadIdx.x == 0) g_bsum[blockIdx.x] = sh[0];
}
// exclusive scan of block sums (single small block)
__global__ void scan2_kernel() {
    __shared__ int sh[SCAN_BLK];
    int t = threadIdx.x;
    int v = (t < NBLK) ? g_bsum[t] : 0;
    sh[t] = v;
    __syncthreads();
    for (int o = 1; o < SCAN_BLK; o <<= 1) {
        int u = (t >= o) ? sh[t - o] : 0;
        __syncthreads();
        sh[t] += u;
        __syncthreads();
    }
    if (t < NBLK) g_boff[t] = sh[t] - v;   // exclusive
}
// per-block exclusive scan + global offset
__global__ void scan3_kernel() {
    __shared__ int sh[SCAN_BLK];
    int t = threadIdx.x;
    int i = blockIdx.x * SCAN_BLK + t;
    int v = (i < NN) ? g_deg[i] : 0;
    sh[t] = v;
    __syncthreads();
    for (int o = 1; o < SCAN_BLK; o <<= 1) {
        int u = (t >= o) ? sh[t - o] : 0;
        __syncthreads();
        sh[t] += u;
        __syncthreads();
    }
    int base = g_boff[blockIdx.x];
    if (i < NN) {
        int off = base + sh[t] - v;
        g_off[i] = off;
        g_cur[i] = off;
        if (i == NN - 1) g_off[NN] = off + v;
    }
}
__global__ void scatter_kernel(const int* __restrict__ ei) {
    int e = blockIdx.x * blockDim.x + threadIdx.x;
    if (e >= ET) return;
    int s, d;
    if (e < EE) { s = ei[e]; d = ei[EE + e]; } else { s = d = e - EE; }
    int pos = atomicAdd(&g_cur[d], 1);
    g_csr[pos] = s;
}

// ================= K1: xl = x @ W  (x:[N,64], W:[64,128]) =================
__global__ void feat_kernel(const float* __restrict__ x, const float* __restrict__ W) {
    __shared__ float ws[64 * 128];    // 32 KB
    __shared__ float xs[64][64];      // 16 KB
    int tid = threadIdx.x;
    int n0 = blockIdx.x * 64;
    for (int i = tid; i < 64 * 128; i += 128) ws[i] = W[i];
    for (int i = tid; i < 64 * 64; i += 128) {
        int r = i >> 6, c = i & 63;
        xs[r][c] = (n0 + r < NN) ? x[(n0 + r) * 64 + c] : 0.f;
    }
    __syncthreads();
    int col = tid;
    float wreg[64];
#pragma unroll
    for (int k = 0; k < 64; k++) wreg[k] = ws[k * 128 + col];
    for (int t = 0; t < 4; t++) {
        float acc[16];
#pragma unroll
        for (int i = 0; i < 16; i++) acc[i] = 0.f;
#pragma unroll
        for (int i = 0; i < 16; i++) {
            const float4* xr = (const float4*)xs[t * 16 + i];
#pragma unroll
            for (int k4 = 0; k4 < 16; k4++) {
                float4 v = xr[k4];
                acc[i] += v.x * wreg[k4 * 4] + v.y * wreg[k4 * 4 + 1]
                        + v.z * wreg[k4 * 4 + 2] + v.w * wreg[k4 * 4 + 3];
            }
        }
        int base = n0 + t * 16;
        int nmax = min(16, NN - base);
        for (int i = 0; i < nmax; i++) g_xl[(base + i) * HXC + col] = acc[i];
    }
}

// ================= K2: per-node attention dots =================
__global__ void att_kernel(const float* __restrict__ att_src, const float* __restrict__ att_dst) {
    int lane = threadIdx.x & 31;
    int n = blockIdx.x * 8 + (threadIdx.x >> 5);
    if (n >= NN) return;
    const float* row = &g_xl[n * HXC];
    float v0 = row[lane], v1 = row[lane + 32], v2 = row[lane + 64], v3 = row[lane + 96];
    float s0 = v0 * att_src[lane] + v1 * att_src[lane + 32];
    float s1 = v2 * att_src[lane + 64] + v3 * att_src[lane + 96];
    float d0 = v0 * att_dst[lane] + v1 * att_dst[lane + 32];
    float d1 = v2 * att_dst[lane + 64] + v3 * att_dst[lane + 96];
#pragma unroll
    for (int o = 16; o > 0; o >>= 1) {
        s0 += __shfl_xor_sync(0xffffffffu, s0, o);
        s1 += __shfl_xor_sync(0xffffffffu, s1, o);
        d0 += __shfl_xor_sync(0xffffffffu, d0, o);
        d1 += __shfl_xor_sync(0xffffffffu, d1, o);
    }
    if (lane == 0) {
        g_asrc[n * 2 + 0] = s0; g_asrc[n * 2 + 1] = s1;
        g_adst[n * 2 + 0] = d0; g_adst[n * 2 + 1] = d1;
    }
}

// ================= K3: fused softmax + gather aggregation (warp per dst) =================
// No max-subtraction (softmax is shift-invariant; alphas are O(1)).
// Inner gather loop unrolled x4 with zero-weight padding for MLP.
__global__ void agg_kernel() {
    int warp = (blockIdx.x * blockDim.x + threadIdx.x) >> 5;
    int lane = threadIdx.x & 31;
    if (warp >= NN) return;
    int n = warp;
    int o0 = g_off[n], o1 = g_off[n + 1];
    int cnt = o1 - o0;
    float2 ad = ((const float2*)g_adst)[n];
    int h = lane >> 4;                   // head for this lane's 4 columns
    float4 acc = make_float4(0.f, 0.f, 0.f, 0.f);
    float dw0 = 0.f, dw1 = 0.f;
    const float4* xl4 = (const float4*)g_xl;

    for (int base = o0; base < o1; base += 32) {
        int c = min(32, o1 - base);
        int s_l = 0;
        float w0_l = 0.f, w1_l = 0.f;
        if (lane < c) {
            s_l = g_csr[base + lane];
            float2 as = ((const float2*)g_asrc)[s_l];
            w0_l = expf(lrelu(as.x + ad.x));
            w1_l = expf(lrelu(as.y + ad.y));
            dw0 += w0_l; dw1 += w1_l;
        }
        int nIter = (c + 3) & ~3;        // padded lanes have w=0, s=0 (safe)
        for (int j = 0; j < nIter; j += 4) {
            int   s[4];
            float w0[4], w1[4];
#pragma unroll
            for (int u = 0; u < 4; u++) {
                s[u]  = __shfl_sync(0xffffffffu, s_l, j + u);
                w0[u] = __shfl_sync(0xffffffffu, w0_l, j + u);
                w1[u] = __shfl_sync(0xffffffffu, w1_l, j + u);
            }
            float4 v[4];
#pragma unroll
            for (int u = 0; u < 4; u++) v[u] = xl4[s[u] * 32 + lane];
#pragma unroll
            for (int u = 0; u < 4; u++) {
                float w = h ? w1[u] : w0[u];
                acc.x += w * v[u].x; acc.y += w * v[u].y;
                acc.z += w * v[u].z; acc.w += w * v[u].w;
            }
        }
    }
#pragma unroll
    for (int o = 16; o > 0; o >>= 1) {
        dw0 += __shfl_xor_sync(0xffffffffu, dw0, o);
        dw1 += __shfl_xor_sync(0xffffffffu, dw1, o);
    }
    float denom = (h ? dw1 : dw0) + 1e-16f;
    float inv = 1.f / denom;
    ((float4*)g_agg)[n * 32 + lane] =
        make_float4(acc.x * inv, acc.y * inv, acc.z * inv, acc.w * inv);
}

// ================= K4: h = elu(agg + bias) @ fcw + fcb  ([N,128] -> [N,64]) =================
__global__ void post_kernel(const float* __restrict__ bias,
                            const float* __restrict__ fcw,
                            const float* __restrict__ fcb) {
    __shared__ float tile[32][128];   // 16 KB
    __shared__ float part[32][64];    // 8 KB
    int tid = threadIdx.x;            // 128
    int n0 = blockIdx.x * 32;
    int col = tid & 63, kh = tid >> 6;
    float fwreg[64];
#pragma unroll
    for (int k = 0; k < 64; k++) fwreg[k] = fcw[(kh * 64 + k) * 64 + col];
    for (int i = tid; i < 32 * 128; i += 128) {
        int r = i >> 7, c = i & 127;
        float v = 0.f;
        if (n0 + r < NN) {
            v = g_agg[(n0 + r) * HXC + c] + bias[c];
            v = (v > 0.f) ? v : expm1f(v);   // ELU
        }
        tile[r][c] = v;
    }
    __syncthreads();
    float acc[32];
#pragma unroll
    for (int i = 0; i < 32; i++) acc[i] = 0.f;
#pragma unroll 4
    for (int i = 0; i < 32; i++) {
        const float4* tr = (const float4*)&tile[i][kh * 64];
#pragma unroll
        for (int k4 = 0; k4 < 16; k4++) {
            float4 v = tr[k4];
            acc[i] += v.x * fwreg[k4 * 4] + v.y * fwreg[k4 * 4 + 1]
                    + v.z * fwreg[k4 * 4 + 2] + v.w * fwreg[k4 * 4 + 3];
        }
    }
    if (kh == 1) {
#pragma unroll 4
        for (int i = 0; i < 32; i++) part[i][col] = acc[i];
    }
    __syncthreads();
    if (kh == 0) {
        int nmax = min(32, NN - n0);
        float b = fcb[col];
        for (int i = 0; i < nmax; i++)
            g_h[(n0 + i) * HIDD + col] = acc[i] + part[i][col] + b;
    }
}

// ================= K5: logits -> gumbel -> softmax (warp per node) =================
__global__ void final_kernel(const float* __restrict__ ow,
                             const float* __restrict__ ob,
                             const float* __restrict__ gu,
                             float* __restrict__ out) {
    __shared__ float ows[64 * 32];
    int tid = threadIdx.x;
    for (int i = tid; i < 64 * 32; i += 256) ows[i] = ow[i];
    __syncthreads();
    int lane = tid & 31;
    int n = blockIdx.x * 8 + (tid >> 5);
    if (n >= NN) return;
    float hlo = g_h[n * HIDD + lane];
    float hhi = g_h[n * HIDD + 32 + lane];
    float acc = ob[lane];
#pragma unroll
    for (int k = 0; k < 32; k++)
        acc += __shfl_sync(0xffffffffu, hlo, k) * ows[k * 32 + lane];
#pragma unroll
    for (int k = 0; k < 32; k++)
        acc += __shfl_sync(0xffffffffu, hhi, k) * ows[(32 + k) * 32 + lane];
    float u = gu[n * OUTD + lane];
    float g = -logf(-logf(u + 1e-20f) + 1e-20f);
    float z = acc + g;   // TEMP = 1
    float m = z;
#pragma unroll
    for (int o = 16; o > 0; o >>= 1) m = fmaxf(m, __shfl_xor_sync(0xffffffffu, m, o));
    float e = expf(z - m);
    float ssum = e;
#pragma unroll
    for (int o = 16; o > 0; o >>= 1) ssum += __shfl_xor_sync(0xffffffffu, ssum, o);
    out[n * OUTD + lane] = e / ssum;
}

// ================= orchestration =================
static void run_gat_layer(const float* x,
                          const float* W, const float* asrc, const float* adst,
                          const float* bias, const float* fcw, const float* fcb) {
    feat_kernel<<<(NN + 63) / 64, 128>>>(x, W);
    att_kernel<<<(NN + 7) / 8, 256>>>(asrc, adst);
    agg_kernel<<<(NN + 7) / 8, 256>>>();
    post_kernel<<<(NN + 31) / 32, 128>>>(bias, fcw, fcb);
}

extern "C" void kernel_launch(void* const* d_in, const int* in_sizes, int n_in,
                              void* d_out, int out_size) {
    const float* x      = (const float*)d_in[0];
    const int*   ei     = (const int*)d_in[1];
    const float* W0     = (const float*)d_in[2];
    const float* asrc0  = (const float*)d_in[3];
    const float* adst0  = (const float*)d_in[4];
    const float* bias0  = (const float*)d_in[5];
    const float* fcw0   = (const float*)d_in[6];
    const float* fcb0   = (const float*)d_in[7];
    const float* W1     = (const float*)d_in[8];
    const float* asrc1  = (const float*)d_in[9];
    const float* adst1  = (const float*)d_in[10];
    const float* bias1  = (const float*)d_in[11];
    const float* fcw1   = (const float*)d_in[12];
    const float* fcb1   = (const float*)d_in[13];
    const float* out_w  = (const float*)d_in[14];
    const float* out_b  = (const float*)d_in[15];
    const float* gu     = (const float*)d_in[16];
    float* out = (float*)d_out;

    // CSR build (edge_index identical for both layers)
    zero_deg_kernel<<<(NN + 255) / 256, 256>>>();
    hist_kernel<<<(EE + 255) / 256, 256>>>(ei);
    scan1_kernel<<<NBLK, SCAN_BLK>>>();
    scan2_kernel<<<1, SCAN_BLK>>>();
    scan3_kernel<<<NBLK, SCAN_BLK>>>();
    scatter_kernel<<<(ET + 255) / 256, 256>>>(ei);

    // Layer 1
    run_gat_layer(x, W0, asrc0, adst0, bias0, fcw0, fcb0);
    // Layer 2 (input = g_h)
    {
        float* hin;
        cudaGetSymbolAddress((void**)&hin, g_h);
        run_gat_layer(hin, W1, asrc1, adst1, bias1, fcw1, fcb1);
    }
    // Final head
    final_kernel<<<(NN + 7) / 8, 256>>>(out_w, out_b, gu, out);
}

// round 5
// speedup vs baseline: 1.9853x; 1.1230x over previous
#include <cuda_runtime.h>
#include <cuda_bf16.h>
#include <cfloat>

// Problem constants (fixed by the dataset)
#define NN 50000
#define EE 800000
#define ET (EE + NN)        // edges + self-loops
#define HXC 128             // H*C = 2*64
#define HIDD 64
#define OUTD 32

#define SCAN_BLK 256
#define NBLK ((NN + SCAN_BLK - 1) / SCAN_BLK)   // 196

// -------- scratch (device globals; no allocation allowed) --------
__device__ float g_xl[NN * HXC];     // transformed features [N,128]
__device__ float g_asrc[NN * 2];     // per-node per-head attention dots
__device__ float g_adst[NN * 2];
__device__ float g_agg[NN * HXC];    // normalized aggregation output
__device__ float g_h[NN * HIDD];     // post-FC hidden
__device__ int   g_deg[NN];          // CSR build
__device__ int   g_off[NN + 1];
__device__ int   g_cur[NN];
__device__ int   g_csr[ET];          // src index per (dst-sorted) edge
__device__ int   g_bsum[NBLK];

__device__ __forceinline__ float lrelu(float x) {
    return (x >= 0.f) ? x : 0.2f * x;
}

// ================= CSR build =================
__global__ void zero_deg_kernel() {
    int i = blockIdx.x * blockDim.x + threadIdx.x;
    if (i < NN) g_deg[i] = 1;   // self-loop
}
__global__ void hist_kernel(const int* __restrict__ ei) {
    int e = blockIdx.x * blockDim.x + threadIdx.x;
    if (e < EE) atomicAdd(&g_deg[ei[EE + e]], 1);
}
// per-block sums
__global__ void scan1_kernel() {
    __shared__ int sh[SCAN_BLK];
    int i = blockIdx.x * SCAN_BLK + threadIdx.x;
    sh[threadIdx.x] = (i < NN) ? g_deg[i] : 0;
    __syncthreads();
    for (int o = SCAN_BLK / 2; o > 0; o >>= 1) {
        if (threadIdx.x < o) sh[threadIdx.x] += sh[threadIdx.x + o];
        __syncthreads();
    }
    if (threadIdx.x == 0) g_bsum[blockIdx.x] = sh[0];
}
// per-block scan; each block also reduces the preceding block sums itself
__global__ void scan3_kernel() {
    __shared__ int sh[SCAN_BLK];
    __shared__ int base_sh;
    int t = threadIdx.x;
    // prefix of block sums before this block
    int acc = 0;
    for (int i = t; i < blockIdx.x; i += SCAN_BLK) acc += g_bsum[i];
    sh[t] = acc;
    __syncthreads();
    for (int o = SCAN_BLK / 2; o > 0; o >>= 1) {
        if (t < o) sh[t] += sh[t + o];
        __syncthreads();
    }
    if (t == 0) base_sh = sh[0];
    __syncthreads();
    int base = base_sh;
    __syncthreads();
    // intra-block inclusive scan (Hillis-Steele)
    int i = blockIdx.x * SCAN_BLK + t;
    int v = (i < NN) ? g_deg[i] : 0;
    sh[t] = v;
    __syncthreads();
    for (int o = 1; o < SCAN_BLK; o <<= 1) {
        int u = (t >= o) ? sh[t - o] : 0;
        __syncthreads();
        sh[t] += u;
        __syncthreads();
    }
    if (i < NN) {
        int off = base + sh[t] - v;
        g_off[i] = off;
        g_cur[i] = off;
        if (i == NN - 1) g_off[NN] = off + v;
    }
}
__global__ void scatter_kernel(const int* __restrict__ ei) {
    int e = blockIdx.x * blockDim.x + threadIdx.x;
    if (e >= ET) return;
    int s, d;
    if (e < EE) { s = ei[e]; d = ei[EE + e]; } else { s = d = e - EE; }
    int pos = atomicAdd(&g_cur[d], 1);
    g_csr[pos] = s;
}

// ================= K1: xl = x @ W + attention dots fused =================
// 64 nodes/block, 128 threads (thread = output col). W column in registers.
// Fully-unrolled accumulators (NO dynamic indexing -> no local spills).
__global__ void featatt_kernel(const float* __restrict__ x, const float* __restrict__ W,
                               const float* __restrict__ att_s, const float* __restrict__ att_d) {
    __shared__ float xs[64][64];      // 16 KB
    __shared__ float red[4][32];      // per-warp attention partials
    int tid = threadIdx.x;
    int n0 = blockIdx.x * 64;
    int lane = tid & 31, wid = tid >> 5;
    for (int i = tid; i < 64 * 64; i += 128) {
        int r = i >> 6, c = i & 63;
        xs[r][c] = (n0 + r < NN) ? x[(n0 + r) * 64 + c] : 0.f;
    }
    int col = tid;
    float wreg[64];
#pragma unroll
    for (int k = 0; k < 64; k++) wreg[k] = W[k * 128 + col];
    float asc = att_s[col], adc = att_d[col];
    __syncthreads();

    for (int t = 0; t < 4; t++) {
        float acc[16];
#pragma unroll
        for (int i = 0; i < 16; i++) acc[i] = 0.f;
#pragma unroll
        for (int i = 0; i < 16; i++) {
            const float4* xr = (const float4*)xs[t * 16 + i];
#pragma unroll
            for (int k4 = 0; k4 < 16; k4++) {
                float4 v = xr[k4];
                acc[i] += v.x * wreg[k4 * 4] + v.y * wreg[k4 * 4 + 1]
                        + v.z * wreg[k4 * 4 + 2] + v.w * wreg[k4 * 4 + 3];
            }
        }
        int nb = n0 + t * 16;
#pragma unroll
        for (int i = 0; i < 16; i++)
            if (nb + i < NN) g_xl[(nb + i) * HXC + col] = acc[i];
        // attention partial dots: reduce acc[i]*att over the 64 cols of each head
#pragma unroll
        for (int i = 0; i < 16; i++) {
            float s = acc[i] * asc, d = acc[i] * adc;
#pragma unroll
            for (int o = 16; o > 0; o >>= 1) {
                s += __shfl_xor_sync(0xffffffffu, s, o);
                d += __shfl_xor_sync(0xffffffffu, d, o);
            }
            if (lane == 0) { red[wid][i * 2] = s; red[wid][i * 2 + 1] = d; }
        }
        __syncthreads();
        if (tid < 64) {
            int i = tid >> 2, h = (tid >> 1) & 1, typ = tid & 1;
            int n = nb + i;
            if (n < NN) {
                float v = red[h * 2][i * 2 + typ] + red[h * 2 + 1][i * 2 + typ];
                if (typ == 0) g_asrc[n * 2 + h] = v;
                else          g_adst[n * 2 + h] = v;
            }
        }
        __syncthreads();
    }
}

// ================= K3: fused softmax + gather aggregation (warp per dst) =================
__global__ void agg_kernel() {
    int warp = (blockIdx.x * blockDim.x + threadIdx.x) >> 5;
    int lane = threadIdx.x & 31;
    if (warp >= NN) return;
    int n = warp;
    int o0 = g_off[n], o1 = g_off[n + 1];
    float2 ad = ((const float2*)g_adst)[n];
    int h = lane >> 4;                   // head for this lane's 4 columns
    float4 acc = make_float4(0.f, 0.f, 0.f, 0.f);
    float dw0 = 0.f, dw1 = 0.f;
    const float4* xl4 = (const float4*)g_xl;

    for (int base = o0; base < o1; base += 32) {
        int c = min(32, o1 - base);
        int s_l = 0;
        float w0_l = 0.f, w1_l = 0.f;
        if (lane < c) {
            s_l = g_csr[base + lane];
            float2 as = ((const float2*)g_asrc)[s_l];
            w0_l = expf(lrelu(as.x + ad.x));
            w1_l = expf(lrelu(as.y + ad.y));
            dw0 += w0_l; dw1 += w1_l;
        }
        int nIter = (c + 3) & ~3;        // padded lanes: w=0, s=0 (safe)
        for (int j = 0; j < nIter; j += 4) {
            int   s[4];
            float w0[4], w1[4];
#pragma unroll
            for (int u = 0; u < 4; u++) {
                s[u]  = __shfl_sync(0xffffffffu, s_l, j + u);
                w0[u] = __shfl_sync(0xffffffffu, w0_l, j + u);
                w1[u] = __shfl_sync(0xffffffffu, w1_l, j + u);
            }
            float4 v[4];
#pragma unroll
            for (int u = 0; u < 4; u++) v[u] = xl4[s[u] * 32 + lane];
#pragma unroll
            for (int u = 0; u < 4; u++) {
                float w = h ? w1[u] : w0[u];
                acc.x += w * v[u].x; acc.y += w * v[u].y;
                acc.z += w * v[u].z; acc.w += w * v[u].w;
            }
        }
    }
#pragma unroll
    for (int o = 16; o > 0; o >>= 1) {
        dw0 += __shfl_xor_sync(0xffffffffu, dw0, o);
        dw1 += __shfl_xor_sync(0xffffffffu, dw1, o);
    }
    float denom = (h ? dw1 : dw0) + 1e-16f;
    float inv = 1.f / denom;
    ((float4*)g_agg)[n * 32 + lane] =
        make_float4(acc.x * inv, acc.y * inv, acc.z * inv, acc.w * inv);
}

// ================= K4: h = elu(agg + bias) @ fcw + fcb  ([N,128] -> [N,64]) =================
// 32 nodes/block, 128 threads (2 k-halves x 64 cols). 8-node chunks keep acc in regs.
__global__ void post_kernel(const float* __restrict__ bias,
                            const float* __restrict__ fcw,
                            const float* __restrict__ fcb) {
    __shared__ float tile[32][128];   // 16 KB
    __shared__ float part[32][64];    // 8 KB
    int tid = threadIdx.x;
    int n0 = blockIdx.x * 32;
    int col = tid & 63, kh = tid >> 6;
    float fwreg[64];
#pragma unroll
    for (int k = 0; k < 64; k++) fwreg[k] = fcw[(kh * 64 + k) * 64 + col];
    for (int i = tid; i < 32 * 128; i += 128) {
        int r = i >> 7, c = i & 127;
        float v = 0.f;
        if (n0 + r < NN) {
            v = g_agg[(n0 + r) * HXC + c] + bias[c];
            v = (v > 0.f) ? v : expm1f(v);   // ELU
        }
        tile[r][c] = v;
    }
    __syncthreads();
    float b = fcb[col];
    for (int ch = 0; ch < 4; ch++) {
        float acc[8];
#pragma unroll
        for (int j = 0; j < 8; j++) acc[j] = 0.f;
#pragma unroll
        for (int j = 0; j < 8; j++) {
            const float4* tr = (const float4*)&tile[ch * 8 + j][kh * 64];
#pragma unroll
            for (int k4 = 0; k4 < 16; k4++) {
                float4 v = tr[k4];
                acc[j] += v.x * fwreg[k4 * 4] + v.y * fwreg[k4 * 4 + 1]
                        + v.z * fwreg[k4 * 4 + 2] + v.w * fwreg[k4 * 4 + 3];
            }
        }
        if (kh == 1) {
#pragma unroll
            for (int j = 0; j < 8; j++) part[ch * 8 + j][col] = acc[j];
        }
        __syncthreads();
        if (kh == 0) {
#pragma unroll
            for (int j = 0; j < 8; j++) {
                int n = n0 + ch * 8 + j;
                if (n < NN) g_h[n * HIDD + col] = acc[j] + part[ch * 8 + j][col] + b;
            }
        }
    }
}

// ================= K5: layer-2 post + logits + gumbel softmax fused =================
__global__ void postfinal_kernel(const float* __restrict__ bias,
                                 const float* __restrict__ fcw,
                                 const float* __restrict__ fcb,
                                 const float* __restrict__ ow,
                                 const float* __restrict__ ob,
                                 const float* __restrict__ gu,
                                 float* __restrict__ out) {
    __shared__ float tile[32][128];   // 16 KB
    __shared__ float part[32][64];    // 8 KB
    __shared__ float h_s[32][64];     // 8 KB
    __shared__ float ows[64 * 32];    // 8 KB
    int tid = threadIdx.x;
    int n0 = blockIdx.x * 32;
    int col = tid & 63, kh = tid >> 6;
    for (int i = tid; i < 64 * 32; i += 128) ows[i] = ow[i];
    float fwreg[64];
#pragma unroll
    for (int k = 0; k < 64; k++) fwreg[k] = fcw[(kh * 64 + k) * 64 + col];
    for (int i = tid; i < 32 * 128; i += 128) {
        int r = i >> 7, c = i & 127;
        float v = 0.f;
        if (n0 + r < NN) {
            v = g_agg[(n0 + r) * HXC + c] + bias[c];
            v = (v > 0.f) ? v : expm1f(v);
        }
        tile[r][c] = v;
    }
    __syncthreads();
    float b = fcb[col];
    for (int ch = 0; ch < 4; ch++) {
        float acc[8];
#pragma unroll
        for (int j = 0; j < 8; j++) acc[j] = 0.f;
#pragma unroll
        for (int j = 0; j < 8; j++) {
            const float4* tr = (const float4*)&tile[ch * 8 + j][kh * 64];
#pragma unroll
            for (int k4 = 0; k4 < 16; k4++) {
                float4 v = tr[k4];
                acc[j] += v.x * fwreg[k4 * 4] + v.y * fwreg[k4 * 4 + 1]
                        + v.z * fwreg[k4 * 4 + 2] + v.w * fwreg[k4 * 4 + 3];
            }
        }
        if (kh == 1) {
#pragma unroll
            for (int j = 0; j < 8; j++) part[ch * 8 + j][col] = acc[j];
        }
        __syncthreads();
        if (kh == 0) {
#pragma unroll
            for (int j = 0; j < 8; j++)
                h_s[ch * 8 + j][col] = acc[j] + part[ch * 8 + j][col] + b;
        }
        __syncthreads();
    }
    // final head: thread t -> node n=t>>2, cols g*8..g*8+7
    int n = tid >> 2, g4 = tid & 3;
    int gn = n0 + n;
    float lg[8];
#pragma unroll
    for (int q = 0; q < 8; q++) lg[q] = ob[g4 * 8 + q];
#pragma unroll
    for (int k = 0; k < 64; k++) {
        float hv = h_s[n][k];
#pragma unroll
        for (int q = 0; q < 8; q++) lg[q] += hv * ows[k * 32 + g4 * 8 + q];
    }
    if (gn < NN) {
        float z[8];
        float m = -FLT_MAX;
#pragma unroll
        for (int q = 0; q < 8; q++) {
            float u = gu[gn * OUTD + g4 * 8 + q];
            float gg = -logf(-logf(u + 1e-20f) + 1e-20f);
            z[q] = lg[q] + gg;
            m = fmaxf(m, z[q]);
        }
        // reduce over the 4-thread group (consecutive lanes)
        m = fmaxf(m, __shfl_xor_sync(0xffffffffu, m, 1, 4));
        m = fmaxf(m, __shfl_xor_sync(0xffffffffu, m, 2, 4));
        float ssum = 0.f;
        float e[8];
#pragma unroll
        for (int q = 0; q < 8; q++) { e[q] = expf(z[q] - m); ssum += e[q]; }
        ssum += __shfl_xor_sync(0xffffffffu, ssum, 1, 4);
        ssum += __shfl_xor_sync(0xffffffffu, ssum, 2, 4);
        float inv = 1.f / ssum;
#pragma unroll
        for (int q = 0; q < 8; q++) out[gn * OUTD + g4 * 8 + q] = e[q] * inv;
    }
}

// ================= orchestration =================
extern "C" void kernel_launch(void* const* d_in, const int* in_sizes, int n_in,
                              void* d_out, int out_size) {
    const float* x      = (const float*)d_in[0];
    const int*   ei     = (const int*)d_in[1];
    const float* W0     = (const float*)d_in[2];
    const float* asrc0  = (const float*)d_in[3];
    const float* adst0  = (const float*)d_in[4];
    const float* bias0  = (const float*)d_in[5];
    const float* fcw0   = (const float*)d_in[6];
    const float* fcb0   = (const float*)d_in[7];
    const float* W1     = (const float*)d_in[8];
    const float* asrc1  = (const float*)d_in[9];
    const float* adst1  = (const float*)d_in[10];
    const float* bias1  = (const float*)d_in[11];
    const float* fcw1   = (const float*)d_in[12];
    const float* fcb1   = (const float*)d_in[13];
    const float* out_w  = (const float*)d_in[14];
    const float* out_b  = (const float*)d_in[15];
    const float* gu     = (const float*)d_in[16];
    float* out = (float*)d_out;

    float* hin;
    cudaGetSymbolAddress((void**)&hin, g_h);

    // CSR build (edge_index identical for both layers)
    zero_deg_kernel<<<(NN + 255) / 256, 256>>>();
    hist_kernel<<<(EE + 255) / 256, 256>>>(ei);
    scan1_kernel<<<NBLK, SCAN_BLK>>>();
    scan3_kernel<<<NBLK, SCAN_BLK>>>();
    scatter_kernel<<<(ET + 255) / 256, 256>>>(ei);

    // Layer 1
    featatt_kernel<<<(NN + 63) / 64, 128>>>(x, W0, asrc0, adst0);
    agg_kernel<<<(NN + 7) / 8, 256>>>();
    post_kernel<<<(NN + 31) / 32, 128>>>(bias0, fcw0, fcb0);
    // Layer 2
    featatt_kernel<<<(NN + 63) / 64, 128>>>(hin, W1, asrc1, adst1);
    agg_kernel<<<(NN + 7) / 8, 256>>>();
    postfinal_kernel<<<(NN + 31) / 32, 128>>>(bias1, fcw1, fcb1, out_w, out_b, gu, out);
}